// round 5
// baseline (speedup 1.0000x reference)
#include <cuda_runtime.h>
#include <math.h>

static constexpr int B_DIM = 8192;
static constexpr int N_PTS = 1024;
static constexpr int THREADS = 256;
static constexpr int ROWS_PER_BLOCK = 2;
static constexpr int GRID = B_DIM / ROWS_PER_BLOCK;   // 4096

// Allocation-free scratch (__device__ globals per harness rules).
__device__ double g_acc;            // zero-init at load; self-reset each launch
__device__ unsigned int g_ticket;   // ditto

__device__ __forceinline__ void euler_to_matrix(float a, float b, float c, float* R) {
    const float sa = sinf(a), ca = cosf(a);
    const float sb = sinf(b), cb = cosf(b);
    const float sc = sinf(c), cc = cosf(c);
    // R = Rx(a) * Ry(b) * Rz(c)
    R[0] = cb * cc;
    R[1] = -cb * sc;
    R[2] = sb;
    R[3] = ca * sc + sa * sb * cc;
    R[4] = ca * cc - sa * sb * sc;
    R[5] = -sa * cb;
    R[6] = sa * sc - ca * sb * cc;
    R[7] = sa * cc + ca * sb * sc;
    R[8] = ca * cb;
}

__device__ __forceinline__ void compute_D(int b, const float* __restrict__ pred,
                                          const float* __restrict__ mode,
                                          const float* __restrict__ gt,
                                          float* __restrict__ Dout) {
    const float m1 = pred[b * 4 + 0];
    const float m2 = pred[b * 4 + 1];
    const float m3 = pred[b * 4 + 2];
    const float m4 = pred[b * 4 + 3];
    const float sgn = (mode[b] > 0.5f) ? 1.0f : -1.0f;
    const float denom = m1 * m1 + m2 * m2 + m3 * m3;
    const float e2 = sgn * asinf(sqrtf(m3 * m3 / denom));
    const float se2 = sinf(e2);
    const float ce2 = cosf(e2);
    const float e3 = atan2f(m4, m3 / (se2 + 1e-9f));
    const float tmp = ce2 * cosf(e3);
    const float e1 = atan2f(m2 / tmp, m1 / tmp);
    // (ref's +2pi wrap of euler3 only shifts by a full period; sin/cos unchanged)

    float Rp[9], Rg[9];
    euler_to_matrix(e1, e2, e3, Rp);
    euler_to_matrix(gt[b * 3 + 0], gt[b * 3 + 1], gt[b * 3 + 2], Rg);
    #pragma unroll
    for (int i = 0; i < 9; i++) Dout[i] = Rp[i] - Rg[i];
}

// q_k = sum over 4 points of || p^T D ||, with 4 points packed in 3 float4s.
__device__ __forceinline__ float norm4(const float4 a, const float4 b, const float4 c,
                                       const float* __restrict__ D) {
    const float d00 = D[0], d01 = D[1], d02 = D[2];
    const float d10 = D[3], d11 = D[4], d12 = D[5];
    const float d20 = D[6], d21 = D[7], d22 = D[8];
    float s = 0.0f;
    const float px[4] = {a.x, a.w, b.z, c.y};
    const float py[4] = {a.y, b.x, b.w, c.z};
    const float pz[4] = {a.z, b.y, c.x, c.w};
    #pragma unroll
    for (int i = 0; i < 4; i++) {
        const float q0 = fmaf(px[i], d00, fmaf(py[i], d10, pz[i] * d20));
        const float q1 = fmaf(px[i], d01, fmaf(py[i], d11, pz[i] * d21));
        const float q2 = fmaf(px[i], d02, fmaf(py[i], d12, pz[i] * d22));
        s += sqrtf(fmaf(q0, q0, fmaf(q1, q1, q2 * q2)));
    }
    return s;
}

__global__ __launch_bounds__(THREADS)
void add_loss_fused_kernel(const float* __restrict__ pred,
                           const float* __restrict__ mode,
                           const float* __restrict__ gt,
                           const float* __restrict__ point,
                           float* __restrict__ out) {
    __shared__ float Dsh[ROWS_PER_BLOCK][9];
    __shared__ float warp_sums[THREADS / 32];

    const int blk = blockIdx.x;
    const int t = threadIdx.x;
    const int b0 = blk * ROWS_PER_BLOCK;

    // Issue ALL global loads first (non-blocking; scoreboard waits at use).
    // Thread t owns floats [12t, 12t+12) of each row = 4 whole points/row.
    const float4* __restrict__ r0 = (const float4*)(point + (size_t)(b0 + 0) * (N_PTS * 3));
    const float4* __restrict__ r1 = (const float4*)(point + (size_t)(b0 + 1) * (N_PTS * 3));
    const float4 a0 = r0[3 * t + 0];
    const float4 b0v = r0[3 * t + 1];
    const float4 c0 = r0[3 * t + 2];
    const float4 a1 = r1[3 * t + 0];
    const float4 b1v = r1[3 * t + 1];
    const float4 c1 = r1[3 * t + 2];

    // Threads 0/1 compute the two D matrices while loads are in flight.
    if (t < ROWS_PER_BLOCK) compute_D(b0 + t, pred, mode, gt, Dsh[t]);
    __syncthreads();

    float sum = norm4(a0, b0v, c0, Dsh[0]) + norm4(a1, b1v, c1, Dsh[1]);

    // Warp reduce
    #pragma unroll
    for (int off = 16; off > 0; off >>= 1)
        sum += __shfl_xor_sync(0xffffffffu, sum, off);
    if ((t & 31) == 0) warp_sums[t >> 5] = sum;
    __syncthreads();

    if (t == 0) {
        float s = 0.0f;
        #pragma unroll
        for (int w = 0; w < THREADS / 32; w++) s += warp_sums[w];
        atomicAdd(&g_acc, (double)s);
        __threadfence();
        const unsigned int ticket = atomicAdd(&g_ticket, 1u);
        if (ticket == (unsigned int)(gridDim.x - 1)) {
            // Last block: all prior partial sums are globally visible.
            __threadfence();
            const double total = atomicAdd(&g_acc, 0.0);
            out[0] = (float)(total * (1.0 / ((double)B_DIM * (double)N_PTS)));
            // Self-reset for the next graph replay (stream-ordered).
            g_acc = 0.0;
            g_ticket = 0u;
        }
    }
}

extern "C" void kernel_launch(void* const* d_in, const int* in_sizes, int n_in,
                              void* d_out, int out_size) {
    const float* pred  = (const float*)d_in[0];   // (8192, 4)
    const float* mode  = (const float*)d_in[1];   // (8192,)
    const float* gt    = (const float*)d_in[2];   // (8192, 3)
    const float* point = (const float*)d_in[3];   // (8192, 1024, 3)
    float* out = (float*)d_out;

    add_loss_fused_kernel<<<GRID, THREADS>>>(pred, mode, gt, point, out);
}

// round 7
// speedup vs baseline: 1.2134x; 1.2134x over previous
#include <cuda_runtime.h>
#include <math.h>

static constexpr int B_DIM = 8192;
static constexpr int N_PTS = 1024;
static constexpr int THREADS = 256;

// Allocation-free scratch (__device__ globals per harness rules).
__device__ double g_acc;
__device__ unsigned int g_ticket;
__device__ float g_D[B_DIM * 9];   // D = R_pred - R_gt per batch row

__device__ __forceinline__ void euler_to_matrix(float a, float b, float c, float* R) {
    const float sa = sinf(a), ca = cosf(a);
    const float sb = sinf(b), cb = cosf(b);
    const float sc = sinf(c), cc = cosf(c);
    // R = Rx(a) * Ry(b) * Rz(c)
    R[0] = cb * cc;
    R[1] = -cb * sc;
    R[2] = sb;
    R[3] = ca * sc + sa * sb * cc;
    R[4] = ca * cc - sa * sb * sc;
    R[5] = -sa * cb;
    R[6] = sa * sc - ca * sb * cc;
    R[7] = sa * cc + ca * sb * sc;
    R[8] = ca * cb;
}

// Kernel 1: per-row trig + matrix difference (8192 parallel threads) + state reset.
__global__ __launch_bounds__(256)
void precompute_kernel(const float* __restrict__ pred,
                       const float* __restrict__ mode,
                       const float* __restrict__ gt) {
    const int b = blockIdx.x * blockDim.x + threadIdx.x;
    if (b == 0) { g_acc = 0.0; g_ticket = 0u; }
    if (b >= B_DIM) return;

    const float m1 = pred[b * 4 + 0];
    const float m2 = pred[b * 4 + 1];
    const float m3 = pred[b * 4 + 2];
    const float m4 = pred[b * 4 + 3];
    const float sgn = (mode[b] > 0.5f) ? 1.0f : -1.0f;
    const float denom = m1 * m1 + m2 * m2 + m3 * m3;
    const float e2 = sgn * asinf(sqrtf(m3 * m3 / denom));
    const float se2 = sinf(e2);
    const float ce2 = cosf(e2);
    const float e3 = atan2f(m4, m3 / (se2 + 1e-9f));
    const float tmp = ce2 * cosf(e3);
    const float e1 = atan2f(m2 / tmp, m1 / tmp);
    // (ref's +2pi wrap of euler3 only shifts by a full period; sin/cos unchanged)

    float Rp[9], Rg[9];
    euler_to_matrix(e1, e2, e3, Rp);
    euler_to_matrix(gt[b * 3 + 0], gt[b * 3 + 1], gt[b * 3 + 2], Rg);
    #pragma unroll
    for (int i = 0; i < 9; i++) g_D[b * 9 + i] = Rp[i] - Rg[i];
}

// Sum of ||p^T D|| over the 4 points packed in 3 consecutive float4s.
__device__ __forceinline__ float norm4(const float4 a, const float4 b, const float4 c,
                                       const float d00, const float d01, const float d02,
                                       const float d10, const float d11, const float d12,
                                       const float d20, const float d21, const float d22) {
    const float px[4] = {a.x, a.w, b.z, c.y};
    const float py[4] = {a.y, b.x, b.w, c.z};
    const float pz[4] = {a.z, b.y, c.x, c.w};
    float s = 0.0f;
    #pragma unroll
    for (int i = 0; i < 4; i++) {
        const float q0 = fmaf(px[i], d00, fmaf(py[i], d10, pz[i] * d20));
        const float q1 = fmaf(px[i], d01, fmaf(py[i], d11, pz[i] * d21));
        const float q2 = fmaf(px[i], d02, fmaf(py[i], d12, pz[i] * d22));
        s += sqrtf(fmaf(q0, q0, fmaf(q1, q1, q2 * q2)));
    }
    return s;
}

// Kernel 2: pure streaming. One row per block, 4 points per thread in registers,
// no trig, no shared staging, no data barrier — warps fully decoupled until the
// final block reduce.
__global__ __launch_bounds__(THREADS)
void add_loss_kernel(const float* __restrict__ point, float* __restrict__ out) {
    __shared__ float warp_sums[THREADS / 32];

    const int b = blockIdx.x;
    const int t = threadIdx.x;

    // Issue the 3 point loads first (independent LDG.128, scoreboard-waited at use).
    const float4* __restrict__ r = (const float4*)(point + (size_t)b * (N_PTS * 3));
    const float4 av = r[3 * t + 0];
    const float4 bv = r[3 * t + 1];
    const float4 cv = r[3 * t + 2];

    // Broadcast D loads (L1-hit after first warp; g_D is L2-warm from kernel 1).
    const float* __restrict__ D = g_D + b * 9;
    const float d00 = __ldg(D + 0), d01 = __ldg(D + 1), d02 = __ldg(D + 2);
    const float d10 = __ldg(D + 3), d11 = __ldg(D + 4), d12 = __ldg(D + 5);
    const float d20 = __ldg(D + 6), d21 = __ldg(D + 7), d22 = __ldg(D + 8);

    float sum = norm4(av, bv, cv, d00, d01, d02, d10, d11, d12, d20, d21, d22);

    // Warp reduce
    #pragma unroll
    for (int off = 16; off > 0; off >>= 1)
        sum += __shfl_xor_sync(0xffffffffu, sum, off);
    if ((t & 31) == 0) warp_sums[t >> 5] = sum;
    __syncthreads();

    if (t == 0) {
        float s = 0.0f;
        #pragma unroll
        for (int w = 0; w < THREADS / 32; w++) s += warp_sums[w];
        atomicAdd(&g_acc, (double)s);
        __threadfence();
        const unsigned int ticket = atomicAdd(&g_ticket, 1u);
        if (ticket == (unsigned int)(gridDim.x - 1)) {
            __threadfence();
            const double total = atomicAdd(&g_acc, 0.0);
            out[0] = (float)(total * (1.0 / ((double)B_DIM * (double)N_PTS)));
        }
    }
}

extern "C" void kernel_launch(void* const* d_in, const int* in_sizes, int n_in,
                              void* d_out, int out_size) {
    const float* pred  = (const float*)d_in[0];   // (8192, 4)
    const float* mode  = (const float*)d_in[1];   // (8192,)
    const float* gt    = (const float*)d_in[2];   // (8192, 3)
    const float* point = (const float*)d_in[3];   // (8192, 1024, 3)
    float* out = (float*)d_out;

    precompute_kernel<<<B_DIM / 256, 256>>>(pred, mode, gt);
    add_loss_kernel<<<B_DIM, THREADS>>>(point, out);
}

// round 8
// speedup vs baseline: 1.4195x; 1.1699x over previous
#include <cuda_runtime.h>
#include <math.h>

static constexpr int B_DIM = 8192;
static constexpr int N_PTS = 1024;
static constexpr int THREADS = 256;
static constexpr int GRID = 888;          // 148 SMs * 6 CTAs/SM, uniform residency

// Allocation-free scratch (__device__ globals per harness rules).
__device__ double g_acc;
__device__ unsigned int g_ticket;
__device__ float g_D[B_DIM * 9];          // D = R_pred - R_gt per batch row

__device__ __forceinline__ void euler_to_matrix(float a, float b, float c, float* R) {
    const float sa = sinf(a), ca = cosf(a);
    const float sb = sinf(b), cb = cosf(b);
    const float sc = sinf(c), cc = cosf(c);
    // R = Rx(a) * Ry(b) * Rz(c)
    R[0] = cb * cc;
    R[1] = -cb * sc;
    R[2] = sb;
    R[3] = ca * sc + sa * sb * cc;
    R[4] = ca * cc - sa * sb * sc;
    R[5] = -sa * cb;
    R[6] = sa * sc - ca * sb * cc;
    R[7] = sa * cc + ca * sb * sc;
    R[8] = ca * cb;
}

// Kernel 1: per-row trig + matrix difference (8192 parallel threads) + state reset.
__global__ __launch_bounds__(256)
void precompute_kernel(const float* __restrict__ pred,
                       const float* __restrict__ mode,
                       const float* __restrict__ gt) {
    const int b = blockIdx.x * blockDim.x + threadIdx.x;
    if (b == 0) { g_acc = 0.0; g_ticket = 0u; }
    if (b >= B_DIM) return;

    const float m1 = pred[b * 4 + 0];
    const float m2 = pred[b * 4 + 1];
    const float m3 = pred[b * 4 + 2];
    const float m4 = pred[b * 4 + 3];
    const float sgn = (mode[b] > 0.5f) ? 1.0f : -1.0f;
    const float denom = m1 * m1 + m2 * m2 + m3 * m3;
    const float e2 = sgn * asinf(sqrtf(m3 * m3 / denom));
    const float se2 = sinf(e2);
    const float ce2 = cosf(e2);
    const float e3 = atan2f(m4, m3 / (se2 + 1e-9f));
    const float tmp = ce2 * cosf(e3);
    const float e1 = atan2f(m2 / tmp, m1 / tmp);
    // (ref's +2pi wrap of euler3 only shifts by a full period; sin/cos unchanged)

    float Rp[9], Rg[9];
    euler_to_matrix(e1, e2, e3, Rp);
    euler_to_matrix(gt[b * 3 + 0], gt[b * 3 + 1], gt[b * 3 + 2], Rg);
    #pragma unroll
    for (int i = 0; i < 9; i++) g_D[b * 9 + i] = Rp[i] - Rg[i];
}

// Kernel 2: persistent streaming. Each CTA grid-strides over rows; each thread
// accumulates across all its rows in a register. ONE reduce + ONE atomic per CTA.
__global__ __launch_bounds__(THREADS, 6)
void add_loss_kernel(const float* __restrict__ point, float* __restrict__ out) {
    __shared__ float warp_sums[THREADS / 32];

    const int t = threadIdx.x;
    float acc = 0.0f;

    for (int b = blockIdx.x; b < B_DIM; b += GRID) {
        // Batch all loads for this row up front (3 LDG.128 + 9 broadcast floats).
        const float4* __restrict__ r = (const float4*)(point + (size_t)b * (N_PTS * 3));
        const float4 av = r[3 * t + 0];
        const float4 bv = r[3 * t + 1];
        const float4 cv = r[3 * t + 2];

        const float* __restrict__ D = g_D + b * 9;
        const float d00 = __ldg(D + 0), d01 = __ldg(D + 1), d02 = __ldg(D + 2);
        const float d10 = __ldg(D + 3), d11 = __ldg(D + 4), d12 = __ldg(D + 5);
        const float d20 = __ldg(D + 6), d21 = __ldg(D + 7), d22 = __ldg(D + 8);

        const float px[4] = {av.x, av.w, bv.z, cv.y};
        const float py[4] = {av.y, bv.x, bv.w, cv.z};
        const float pz[4] = {av.z, bv.y, cv.x, cv.w};
        #pragma unroll
        for (int i = 0; i < 4; i++) {
            const float q0 = fmaf(px[i], d00, fmaf(py[i], d10, pz[i] * d20));
            const float q1 = fmaf(px[i], d01, fmaf(py[i], d11, pz[i] * d21));
            const float q2 = fmaf(px[i], d02, fmaf(py[i], d12, pz[i] * d22));
            acc += sqrtf(fmaf(q0, q0, fmaf(q1, q1, q2 * q2)));
        }
    }

    // One reduce + one atomic per CTA (tail amortized over ~9 rows).
    #pragma unroll
    for (int off = 16; off > 0; off >>= 1)
        acc += __shfl_xor_sync(0xffffffffu, acc, off);
    if ((t & 31) == 0) warp_sums[t >> 5] = acc;
    __syncthreads();

    if (t == 0) {
        float s = 0.0f;
        #pragma unroll
        for (int w = 0; w < THREADS / 32; w++) s += warp_sums[w];
        atomicAdd(&g_acc, (double)s);
        __threadfence();
        const unsigned int ticket = atomicAdd(&g_ticket, 1u);
        if (ticket == (unsigned int)(gridDim.x - 1)) {
            __threadfence();
            const double total = atomicAdd(&g_acc, 0.0);
            out[0] = (float)(total * (1.0 / ((double)B_DIM * (double)N_PTS)));
        }
    }
}

extern "C" void kernel_launch(void* const* d_in, const int* in_sizes, int n_in,
                              void* d_out, int out_size) {
    const float* pred  = (const float*)d_in[0];   // (8192, 4)
    const float* mode  = (const float*)d_in[1];   // (8192,)
    const float* gt    = (const float*)d_in[2];   // (8192, 3)
    const float* point = (const float*)d_in[3];   // (8192, 1024, 3)
    float* out = (float*)d_out;

    precompute_kernel<<<B_DIM / 256, 256>>>(pred, mode, gt);
    add_loss_kernel<<<GRID, THREADS>>>(point, out);
}